// round 14
// baseline (speedup 1.0000x reference)
#include <cuda_runtime.h>
#include <cstdint>

// ---------------------------------------------------------------------------
// TwoDRNN (mma.sync tf32, sm_103-safe): h = h1@U1 + h2@U2 ; GRU(h,x) -> out x2
// R14: TILE_M=128, 256 thr, warp tile m32n64, 1 CTA/SM, gates in registers.
//      B operands pre-packed as (k,k+4) float2 pairs -> 1 LDS.64 per fragment.
//      W double-buffered via cp.async (10 K=64 phases, one sync per phase).
// ---------------------------------------------------------------------------

#define DHID 128
#define TILE_M 128
#define NTHREADS 256

constexpr int LDA = 132;                        // A/H rows: banks 4g+ctg, conflict-free

// smem layout (floats)
constexpr int OFF_AH  = 0;                      // 128 x 132
constexpr int OFF_W0  = OFF_AH + TILE_M * LDA;  // 16896
constexpr int OFF_W1  = OFF_W0 + 8192;          // 25088
constexpr int OFF_X   = OFF_W1 + 8192;          // 33280
constexpr int OFF_WI  = OFF_X  + 512;           // 33792
constexpr int OFF_BI  = OFF_WI + 1536;          // 35328
constexpr int OFF_BHN = OFF_BI + 384;           // 35712
constexpr int SMEM_FLOATS = OFF_BHN + 128;      // 35840
constexpr int SMEM_BYTES  = SMEM_FLOATS * 4;    // 143360 B -> 1 CTA/SM

// Pre-rounded tf32 weight half-images (K=64 each), pair-packed:
// img = phase p: {U1k0,U1k1,U2k0,U2k1,Whr k0,k1,Whn k0,k1,Whz k0,k1}
// float2 {W[k0+pk][n], W[k0+pk+4][n]} at float offset ks*1024 + n*8 + pk*2
__device__ float g_w[10][8192];

__device__ __forceinline__ unsigned f2tf(float x) {
    unsigned u;
    asm("cvt.rna.tf32.f32 %0, %1;" : "=r"(u) : "f"(x));
    return u;
}

__device__ __forceinline__ void mma8(float* d, unsigned a0, unsigned a1,
                                     unsigned a2, unsigned a3,
                                     unsigned b0, unsigned b1) {
    asm volatile(
        "mma.sync.aligned.m16n8k8.row.col.f32.tf32.tf32.f32 "
        "{%0,%1,%2,%3}, {%4,%5,%6,%7}, {%8,%9}, {%0,%1,%2,%3};"
        : "+f"(d[0]), "+f"(d[1]), "+f"(d[2]), "+f"(d[3])
        : "r"(a0), "r"(a1), "r"(a2), "r"(a3), "r"(b0), "r"(b1));
}

__device__ __forceinline__ float sigmoidf_(float v) {
    return 1.0f / (1.0f + __expf(-v));
}
__device__ __forceinline__ float tanhf_(float v) {
    float c = fminf(fmaxf(v, -15.0f), 15.0f);
    float e = __expf(2.0f * c);
    return (e - 1.0f) / (e + 1.0f);
}

__device__ __forceinline__ void cp16(void* s, const void* g) {
    unsigned sa = (unsigned)__cvta_generic_to_shared(s);
    asm volatile("cp.async.ca.shared.global [%0], [%1], 16;" :: "r"(sa), "l"(g));
}
__device__ __forceinline__ void cp_commit() { asm volatile("cp.async.commit_group;"); }
template <int N>
__device__ __forceinline__ void cp_wait() {
    asm volatile("cp.async.wait_group %0;" :: "n"(N) : "memory");
}

// cp.async one 32KB pre-imaged weight half (contiguous).
__device__ __forceinline__ void cp_w(float* sW, const float* __restrict__ g, int tid) {
#pragma unroll
    for (int it = 0; it < 8; ++it) {
        int i = it * NTHREADS + tid;            // 0..2047 float4 slots
        cp16(sW + i * 4, g + i * 4);
    }
    cp_commit();
}

// Build 128x128 A tile (LDG + tf32 round + STS), plain layout LDA=132.
__device__ __forceinline__ void build_a(float* sAH, const float* __restrict__ g, int tid) {
#pragma unroll
    for (int it = 0; it < 16; ++it) {
        int i  = it * NTHREADS + tid;
        int r  = i >> 5;
        int c4 = (i & 31) << 2;
        float4 v = *reinterpret_cast<const float4*>(g + (long)r * DHID + c4);
        v.x = __uint_as_float(f2tf(v.x));
        v.y = __uint_as_float(f2tf(v.y));
        v.z = __uint_as_float(f2tf(v.z));
        v.w = __uint_as_float(f2tf(v.w));
        *reinterpret_cast<float4*>(sAH + r * LDA + c4) = v;
    }
}

// acc += A[mBase:+32, kA0*8 : +64] @ Whalf[:, nBase:+64]  (8 K8-steps)
// acc[(mt*8+t)*4 + q].  CVTA: round A in-loop (stage-2, A = fp32 h).
template <bool CVTA>
__device__ __forceinline__ void gemm_half(const float* sA, const float* sW,
                                          float acc[64], int kA0,
                                          int mBase, int nBase, int g, int ctg) {
#pragma unroll
    for (int ks = 0; ks < 8; ++ks) {
        const int kA = (kA0 + ks) * 8;
        unsigned a[2][4];
#pragma unroll
        for (int mt = 0; mt < 2; ++mt) {
            const float* ar0 = sA + (mBase + mt * 16 + g) * LDA + kA;
            const float* ar1 = ar0 + 8 * LDA;
            if (CVTA) {
                a[mt][0] = f2tf(ar0[ctg]);
                a[mt][1] = f2tf(ar1[ctg]);
                a[mt][2] = f2tf(ar0[ctg + 4]);
                a[mt][3] = f2tf(ar1[ctg + 4]);
            } else {
                a[mt][0] = __float_as_uint(ar0[ctg]);
                a[mt][1] = __float_as_uint(ar1[ctg]);
                a[mt][2] = __float_as_uint(ar0[ctg + 4]);
                a[mt][3] = __float_as_uint(ar1[ctg + 4]);
            }
        }
        const float* bp = sW + ks * 1024 + (nBase + g) * 8 + ctg * 2;
#pragma unroll
        for (int t = 0; t < 8; ++t) {
            float2 b = *reinterpret_cast<const float2*>(bp + t * 64);
            unsigned b0 = __float_as_uint(b.x);
            unsigned b1 = __float_as_uint(b.y);
            mma8(acc + (0 * 8 + t) * 4, a[0][0], a[0][1], a[0][2], a[0][3], b0, b1);
            mma8(acc + (1 * 8 + t) * 4, a[1][0], a[1][1], a[1][2], a[1][3], b0, b1);
        }
    }
}

// GRU epilogue for chunk CH (0: r, 1: n in-place, 2: z + blend into sAH).
template <int CH>
__device__ __forceinline__ void epilogue(const float acc[64], float gate[64],
                                         float* sAH, const float* sX,
                                         const float* sWi, const float* sBi,
                                         const float* sBhn,
                                         int mBase, int nBase, int g, int ctg) {
    float xv[4][4];
#pragma unroll
    for (int mt = 0; mt < 2; ++mt)
#pragma unroll
        for (int qh = 0; qh < 2; ++qh) {
            int rr = mBase + mt * 16 + g + qh * 8;
#pragma unroll
            for (int k = 0; k < 4; ++k) xv[mt * 2 + qh][k] = sX[rr * 4 + k];
        }
#pragma unroll
    for (int t = 0; t < 8; ++t) {
#pragma unroll
        for (int ql = 0; ql < 2; ++ql) {
            const int cc = nBase + t * 8 + 2 * ctg + ql;
            const int j  = cc + (CH == 0 ? 0 : (CH == 1 ? 256 : 128));
            const float w0 = sWi[0 * 384 + j];
            const float w1 = sWi[1 * 384 + j];
            const float w2 = sWi[2 * 384 + j];
            const float w3 = sWi[3 * 384 + j];
            const float bb = sBi[j];
            const float bh = (CH == 1) ? sBhn[cc] : 0.0f;
#pragma unroll
            for (int mt = 0; mt < 2; ++mt)
#pragma unroll
                for (int qh = 0; qh < 2; ++qh) {
                    const int idx = (mt * 8 + t) * 4 + qh * 2 + ql;
                    const float* xp = xv[mt * 2 + qh];
                    float ip = bb + xp[0] * w0 + xp[1] * w1
                                  + xp[2] * w2 + xp[3] * w3;
                    const float v = acc[idx];
                    if (CH == 0) {
                        gate[idx] = sigmoidf_(ip + v);                  // r
                    } else if (CH == 1) {
                        gate[idx] = tanhf_(ip + gate[idx] * (v + bh));  // n
                    } else {
                        const int rr = mBase + mt * 16 + g + qh * 8;
                        float z  = sigmoidf_(ip + v);
                        float hv = sAH[rr * LDA + cc];
                        sAH[rr * LDA + cc] = (1.0f - z) * gate[idx] + z * hv;
                    }
                }
        }
    }
}

// Offline: round weights to tf32-rna, pair-pack (k, k+4) as float2 images.
__global__ void preround(const float* __restrict__ U1, const float* __restrict__ U2,
                         const float* __restrict__ Whrz, const float* __restrict__ Whn) {
    const int idx = blockIdx.x * blockDim.x + threadIdx.x;   // < 81920
    const int img  = idx >> 13;          // 0..9
    const int o    = idx & 8191;
    const int ks   = o >> 10;
    const int q    = o & 1023;
    const int n    = q >> 3;
    const int w    = q & 7;
    const int pk   = w >> 1;
    const int c    = w & 1;
    const int gi   = img >> 1;
    const int half = img & 1;
    const int k    = half * 64 + ks * 8 + pk + 4 * c;
    float v;
    if      (gi == 0) v = U1[k * 128 + n];
    else if (gi == 1) v = U2[k * 128 + n];
    else if (gi == 2) v = Whrz[k * 256 + n];
    else if (gi == 3) v = Whn[k * 128 + n];
    else              v = Whrz[k * 256 + 128 + n];
    g_w[img][o] = __uint_as_float(f2tf(v));
}

__global__ __launch_bounds__(NTHREADS, 1)
void twodrnn_kernel(const float* __restrict__ x,
                    const float* __restrict__ h1,
                    const float* __restrict__ h2,
                    const float* __restrict__ Wi,
                    const float* __restrict__ bi,
                    const float* __restrict__ bhn,
                    float* __restrict__ out, long dup_off) {
    extern __shared__ float sm[];
    float* sAH  = sm + OFF_AH;
    float* sW0  = sm + OFF_W0;
    float* sW1  = sm + OFF_W1;
    float* sX   = sm + OFF_X;
    float* sWi  = sm + OFF_WI;
    float* sBi  = sm + OFF_BI;
    float* sBhn = sm + OFF_BHN;

    const int tid  = threadIdx.x;
    const int warp = tid >> 5;
    const int lane = tid & 31;
    const int g    = lane >> 2;
    const int ctg  = lane & 3;
    const int mBase = (warp & 3) * 32;
    const int nBase = (warp >> 2) * 64;
    const long rowBase = (long)blockIdx.x * TILE_M;

    // groups 0,1: first two weight halves; build A(h1); small params
    cp_w(sW0, g_w[0], tid);
    cp_w(sW1, g_w[1], tid);
    build_a(sAH, h1 + rowBase * DHID, tid);
    for (int i = tid; i < 1536; i += NTHREADS) sWi[i] = Wi[i];
    for (int i = tid; i < 384; i += NTHREADS)  sBi[i] = bi[i];
    for (int i = tid; i < 128; i += NTHREADS)  sBhn[i] = bhn[i];
    for (int i = tid; i < TILE_M * 4; i += NTHREADS) sX[i] = x[rowBase * 4 + i];
    cp_wait<1>();
    __syncthreads();

    float acc[64];
#pragma unroll
    for (int i = 0; i < 64; ++i) acc[i] = 0.0f;

    // p0: h1 @ U1[k 0:64]
    gemm_half<false>(sAH, sW0, acc, 0, mBase, nBase, g, ctg);
    __syncthreads();
    cp_w(sW0, g_w[2], tid);                 // group 2
    cp_wait<1>();
    __syncthreads();

    // p1: h1 @ U1[k 64:128]
    gemm_half<false>(sAH, sW1, acc, 8, mBase, nBase, g, ctg);
    __syncthreads();
    cp_w(sW1, g_w[3], tid);                 // group 3
    build_a(sAH, h2 + rowBase * DHID, tid); // A reads done -> overwrite with h2
    cp_wait<1>();
    __syncthreads();

    // p2: += h2 @ U2[k 0:64]
    gemm_half<false>(sAH, sW0, acc, 0, mBase, nBase, g, ctg);
    __syncthreads();
    cp_w(sW0, g_w[4], tid);                 // group 4
    cp_wait<1>();
    __syncthreads();

    // p3: += h2 @ U2[k 64:128]
    gemm_half<false>(sAH, sW1, acc, 8, mBase, nBase, g, ctg);
    __syncthreads();                        // all A reads done

    // stage h (fp32) into sAH
#pragma unroll
    for (int mt = 0; mt < 2; ++mt)
#pragma unroll
        for (int t = 0; t < 8; ++t) {
            const float* a4 = acc + (mt * 8 + t) * 4;
            int r0 = mBase + mt * 16 + g;
            int c  = nBase + t * 8 + 2 * ctg;
            *reinterpret_cast<float2*>(&sAH[r0 * LDA + c]) = make_float2(a4[0], a4[1]);
            *reinterpret_cast<float2*>(&sAH[(r0 + 8) * LDA + c]) = make_float2(a4[2], a4[3]);
        }
    cp_w(sW1, g_w[5], tid);                 // group 5
    cp_wait<1>();
    __syncthreads();                        // h visible

    float gate[64];

    // ---- chunk r (p4, p5) ----
#pragma unroll
    for (int i = 0; i < 64; ++i) acc[i] = 0.0f;
    gemm_half<true>(sAH, sW0, acc, 0, mBase, nBase, g, ctg);
    __syncthreads();
    cp_w(sW0, g_w[6], tid);                 // group 6
    cp_wait<1>();
    __syncthreads();
    gemm_half<true>(sAH, sW1, acc, 8, mBase, nBase, g, ctg);
    epilogue<0>(acc, gate, sAH, sX, sWi, sBi, sBhn, mBase, nBase, g, ctg);
    __syncthreads();
    cp_w(sW1, g_w[7], tid);                 // group 7
    cp_wait<1>();
    __syncthreads();

    // ---- chunk n (p6, p7) ----
#pragma unroll
    for (int i = 0; i < 64; ++i) acc[i] = 0.0f;
    gemm_half<true>(sAH, sW0, acc, 0, mBase, nBase, g, ctg);
    __syncthreads();
    cp_w(sW0, g_w[8], tid);                 // group 8
    cp_wait<1>();
    __syncthreads();
    gemm_half<true>(sAH, sW1, acc, 8, mBase, nBase, g, ctg);
    epilogue<1>(acc, gate, sAH, sX, sWi, sBi, sBhn, mBase, nBase, g, ctg);
    __syncthreads();
    cp_w(sW1, g_w[9], tid);                 // group 9
    cp_wait<1>();
    __syncthreads();

    // ---- chunk z (p8, p9) ----
#pragma unroll
    for (int i = 0; i < 64; ++i) acc[i] = 0.0f;
    gemm_half<true>(sAH, sW0, acc, 0, mBase, nBase, g, ctg);
    cp_wait<0>();                           // group 9 fully landed
    __syncthreads();
    gemm_half<true>(sAH, sW1, acc, 8, mBase, nBase, g, ctg);
    __syncthreads();                        // all gemm A-reads done before blend writes
    epilogue<2>(acc, gate, sAH, sX, sWi, sBi, sBhn, mBase, nBase, g, ctg);
    __syncthreads();

    // coalesced writeback (x2 for the (new_h, new_h) tuple)
    float* o0 = out + rowBase * DHID;
#pragma unroll
    for (int it = 0; it < 16; ++it) {
        int i  = it * NTHREADS + tid;
        int r  = i >> 5;
        int c4 = (i & 31) << 2;
        float4 v = *reinterpret_cast<const float4*>(sAH + r * LDA + c4);
        *reinterpret_cast<float4*>(o0 + (long)r * DHID + c4) = v;
        if (dup_off)
            *reinterpret_cast<float4*>(o0 + dup_off + (long)r * DHID + c4) = v;
    }
}

extern "C" void kernel_launch(void* const* d_in, const int* in_sizes, int n_in,
                              void* d_out, int out_size) {
    cudaFuncSetAttribute(twodrnn_kernel,
                         cudaFuncAttributeMaxDynamicSharedMemorySize, SMEM_BYTES);

    const float* x    = (const float*)d_in[0];
    const float* h1   = (const float*)d_in[1];
    const float* h2   = (const float*)d_in[2];
    const float* U1   = (const float*)d_in[3];
    const float* U2   = (const float*)d_in[4];
    const float* Wi   = (const float*)d_in[5];
    const float* bi   = (const float*)d_in[6];
    const float* Whrz = (const float*)d_in[7];
    const float* Whn  = (const float*)d_in[8];
    const float* bhn  = (const float*)d_in[9];

    const int Brows = in_sizes[1] / DHID;            // 262144
    const int grid  = Brows / TILE_M;                // 2048
    const long base = (long)Brows * DHID;
    const long dup_off = ((long)out_size >= 2 * base) ? base : 0;

    preround<<<640, 128>>>(U1, U2, Whrz, Whn);
    twodrnn_kernel<<<grid, NTHREADS, SMEM_BYTES>>>(
        x, h1, h2, Wi, bi, bhn, (float*)d_out, dup_off);
}

// round 15
// speedup vs baseline: 1.1928x; 1.1928x over previous
#include <cuda_runtime.h>
#include <cstdint>

// ---------------------------------------------------------------------------
// TwoDRNN (mma.sync tf32): h = h1@U1 + h2@U2 ; GRU(h,x) -> new_h (x2)
// R15: TILE_M=64, 256 thr, m16n64 warp tile, 2 CTAs/SM (16 warps/SM).
//      B pre-packed as float4 quads -> 1 LDS.128 per 2 MMAs, conflict-free.
//      Weights in K=64 half-images, double-buffered cp.async (10 phases),
//      each load streams under the previous phase's gemm. h tiles via cp.async.
// ---------------------------------------------------------------------------

#define DHID 128
#define TILE_M 64
#define NTHREADS 256

constexpr int LDA = 132;                        // A/H rows: banks 4g+ctg conflict-free

// smem layout (floats)
constexpr int OFF_AH  = 0;                      // 64 x 132 (h tile / h fp32)
constexpr int OFF_W0  = OFF_AH + TILE_M * LDA;  // 8448   (8192: K=64 half image)
constexpr int OFF_W1  = OFF_W0 + 8192;          // 16640
constexpr int OFF_X   = OFF_W1 + 8192;          // 24832
constexpr int OFF_WI  = OFF_X  + TILE_M * 4;    // 25088
constexpr int OFF_BI  = OFF_WI + 1536;          // 26624
constexpr int OFF_BHN = OFF_BI + 384;           // 27008
constexpr int SMEM_FLOATS = OFF_BHN + 128;      // 27136
constexpr int SMEM_BYTES  = SMEM_FLOATS * 4;    // 108544 B -> 2 CTAs/SM

// Pre-rounded tf32 weight half-images (K=64, N=128), float4-quad packed:
// imgs: 0,1: U1 k0,k1  2,3: U2  4,5: Whr  6,7: Whn  8,9: Whz
// float offset = ks*1024 + ng*128 + g*16 + ctg*4 + c, quad c =
//   {W[kb+ctg][n], W[kb+ctg+4][n], W[kb+ctg][n+8], W[kb+ctg+4][n+8]},
//   n = ng*16 + g, kb = half*64 + ks*8.
__device__ float g_w[10][8192];

__device__ __forceinline__ unsigned f2tf(float x) {
    unsigned u;
    asm("cvt.rna.tf32.f32 %0, %1;" : "=r"(u) : "f"(x));
    return u;
}

__device__ __forceinline__ void mma8(float* d, unsigned a0, unsigned a1,
                                     unsigned a2, unsigned a3,
                                     unsigned b0, unsigned b1) {
    asm volatile(
        "mma.sync.aligned.m16n8k8.row.col.f32.tf32.tf32.f32 "
        "{%0,%1,%2,%3}, {%4,%5,%6,%7}, {%8,%9}, {%0,%1,%2,%3};"
        : "+f"(d[0]), "+f"(d[1]), "+f"(d[2]), "+f"(d[3])
        : "r"(a0), "r"(a1), "r"(a2), "r"(a3), "r"(b0), "r"(b1));
}

__device__ __forceinline__ float sigmoidf_(float v) {
    return 1.0f / (1.0f + __expf(-v));
}
__device__ __forceinline__ float tanhf_(float v) {
    float c = fminf(fmaxf(v, -15.0f), 15.0f);
    float e = __expf(2.0f * c);
    return (e - 1.0f) / (e + 1.0f);
}

__device__ __forceinline__ void cp16(void* s, const void* g) {
    unsigned sa = (unsigned)__cvta_generic_to_shared(s);
    asm volatile("cp.async.ca.shared.global [%0], [%1], 16;" :: "r"(sa), "l"(g));
}
__device__ __forceinline__ void cp_commit() { asm volatile("cp.async.commit_group;"); }
template <int N>
__device__ __forceinline__ void cp_wait() {
    asm volatile("cp.async.wait_group %0;" :: "n"(N) : "memory");
}

// cp.async one 32KB pre-imaged weight half (contiguous). Commits a group.
__device__ __forceinline__ void cp_w(float* sW, const float* __restrict__ g, int tid) {
#pragma unroll
    for (int it = 0; it < 8; ++it) {
        int i = it * NTHREADS + tid;            // 2048 float4 slots
        cp16(sW + i * 4, g + i * 4);
    }
    cp_commit();
}

// cp.async a 64x128 fp32 h tile into sAH (stride LDA). Commits a group.
__device__ __forceinline__ void cp_h(float* sAH, const float* __restrict__ g, int tid) {
#pragma unroll
    for (int it = 0; it < 8; ++it) {
        int i  = it * NTHREADS + tid;           // 2048 float4 slots
        int r  = i >> 5;
        int c4 = (i & 31) << 2;
        cp16(sAH + r * LDA + c4, g + (long)r * DHID + c4);
    }
    cp_commit();
}

// acc += A[mBase:+16, kA0:+64] @ Whalf[:, nBase:+64]  (8 k8-steps).
// A raw fp32 in smem, rna-rounded in-loop. B via LDS.128 quads.
__device__ __forceinline__ void gemm_half(const float* sA, const float* sW,
                                          float acc[32], int kA0,
                                          int mBase, int nBase, int g, int ctg) {
    const int ngBase = nBase >> 4;              // 0 or 4
#pragma unroll
    for (int ks = 0; ks < 8; ++ks) {
        const int kA = kA0 + ks * 8;
        const float* ar0 = sA + (mBase + g) * LDA + kA;
        const float* ar1 = ar0 + 8 * LDA;
        unsigned a0 = f2tf(ar0[ctg]);
        unsigned a1 = f2tf(ar1[ctg]);
        unsigned a2 = f2tf(ar0[ctg + 4]);
        unsigned a3 = f2tf(ar1[ctg + 4]);
        const float* bp = sW + ks * 1024 + ngBase * 128 + g * 16 + ctg * 4;
#pragma unroll
        for (int tp = 0; tp < 4; ++tp) {
            float4 b = *reinterpret_cast<const float4*>(bp + tp * 128);
            mma8(acc + (2 * tp) * 4, a0, a1, a2, a3,
                 __float_as_uint(b.x), __float_as_uint(b.y));
            mma8(acc + (2 * tp + 1) * 4, a0, a1, a2, a3,
                 __float_as_uint(b.z), __float_as_uint(b.w));
        }
    }
}

// GRU epilogue for chunk CH (0: r, 1: n in-place, 2: z + blend into sAH).
template <int CH>
__device__ __forceinline__ void epilogue(const float acc[32], float gate[32],
                                         float* sAH, const float* sX,
                                         const float* sWi, const float* sBi,
                                         const float* sBhn,
                                         int mBase, int nBase, int g, int ctg) {
    float xv[2][4];
#pragma unroll
    for (int qh = 0; qh < 2; ++qh) {
        int rr = mBase + g + qh * 8;
#pragma unroll
        for (int k = 0; k < 4; ++k) xv[qh][k] = sX[rr * 4 + k];
    }
#pragma unroll
    for (int t = 0; t < 8; ++t) {
#pragma unroll
        for (int ql = 0; ql < 2; ++ql) {
            const int cc = nBase + t * 8 + 2 * ctg + ql;
            const int j  = cc + (CH == 0 ? 0 : (CH == 1 ? 256 : 128));
            const float w0 = sWi[0 * 384 + j];
            const float w1 = sWi[1 * 384 + j];
            const float w2 = sWi[2 * 384 + j];
            const float w3 = sWi[3 * 384 + j];
            const float bb = sBi[j];
            const float bh = (CH == 1) ? sBhn[cc] : 0.0f;
#pragma unroll
            for (int qh = 0; qh < 2; ++qh) {
                const int idx = t * 4 + qh * 2 + ql;
                const float* xp = xv[qh];
                float ip = bb + xp[0] * w0 + xp[1] * w1
                              + xp[2] * w2 + xp[3] * w3;
                const float v = acc[idx];
                if (CH == 0) {
                    gate[idx] = sigmoidf_(ip + v);                  // r
                } else if (CH == 1) {
                    gate[idx] = tanhf_(ip + gate[idx] * (v + bh));  // n
                } else {
                    const int rr = mBase + g + qh * 8;
                    float z  = sigmoidf_(ip + v);
                    float hv = sAH[rr * LDA + cc];
                    sAH[rr * LDA + cc] = (1.0f - z) * gate[idx] + z * hv;
                }
            }
        }
    }
}

// Offline: round weights to tf32-rna and pack float4 quads.
__global__ void preround(const float* __restrict__ U1, const float* __restrict__ U2,
                         const float* __restrict__ Whrz, const float* __restrict__ Whn) {
    const int idx = blockIdx.x * blockDim.x + threadIdx.x;   // < 81920
    const int img  = idx >> 13;         // 0..9
    const int o    = idx & 8191;
    const int ks   = o >> 10;
    const int r    = o & 1023;
    const int ng   = r >> 7;
    const int q    = r & 127;
    const int g    = q >> 4;
    const int w    = q & 15;
    const int ctg  = w >> 2;
    const int c    = w & 3;
    const int gi   = img >> 1;
    const int half = img & 1;
    const int n    = ng * 16 + g + (c >> 1) * 8;
    const int k    = half * 64 + ks * 8 + ctg + (c & 1) * 4;
    float v;
    if      (gi == 0) v = U1[k * 128 + n];
    else if (gi == 1) v = U2[k * 128 + n];
    else if (gi == 2) v = Whrz[k * 256 + n];
    else if (gi == 3) v = Whn[k * 128 + n];
    else              v = Whrz[k * 256 + 128 + n];
    g_w[img][o] = __uint_as_float(f2tf(v));
}

__global__ __launch_bounds__(NTHREADS, 2)
void twodrnn_kernel(const float* __restrict__ x,
                    const float* __restrict__ h1,
                    const float* __restrict__ h2,
                    const float* __restrict__ Wi,
                    const float* __restrict__ bi,
                    const float* __restrict__ bhn,
                    float* __restrict__ out, long dup_off) {
    extern __shared__ float sm[];
    float* sAH  = sm + OFF_AH;
    float* sW0  = sm + OFF_W0;
    float* sW1  = sm + OFF_W1;
    float* sX   = sm + OFF_X;
    float* sWi  = sm + OFF_WI;
    float* sBi  = sm + OFF_BI;
    float* sBhn = sm + OFF_BHN;

    const int tid  = threadIdx.x;
    const int warp = tid >> 5;
    const int lane = tid & 31;
    const int g    = lane >> 2;
    const int ctg  = lane & 3;
    const int mBase = (warp & 3) * 16;   // 4 m-tiles
    const int nBase = (warp >> 2) * 64;  // 2 n-halves
    const long rowBase = (long)blockIdx.x * TILE_M;

    // prologue: h1 (group), img0 (group), img1 (group), small params
    cp_h(sAH, h1 + rowBase * DHID, tid);
    cp_w(sW0, g_w[0], tid);
    cp_w(sW1, g_w[1], tid);
    for (int i = tid; i < 1536; i += NTHREADS) sWi[i] = Wi[i];
    for (int i = tid; i < 384; i += NTHREADS)  sBi[i] = bi[i];
    for (int i = tid; i < 128; i += NTHREADS)  sBhn[i] = bhn[i];
    for (int i = tid; i < TILE_M * 4; i += NTHREADS) sX[i] = x[rowBase * 4 + i];
    cp_wait<1>();                      // h1 + img0 landed (img1 in flight)
    __syncthreads();

    float acc[32];
#pragma unroll
    for (int i = 0; i < 32; ++i) acc[i] = 0.0f;

    // p0: h1 @ U1[k0]
    gemm_half(sAH, sW0, acc, 0, mBase, nBase, g, ctg);
    __syncthreads();
    cp_w(sW0, g_w[2], tid);
    cp_wait<1>();                      // img1 ready
    __syncthreads();

    // p1: h1 @ U1[k1]
    gemm_half(sAH, sW1, acc, 64, mBase, nBase, g, ctg);
    __syncthreads();                   // h1 reads done
    cp_h(sAH, h2 + rowBase * DHID, tid);   // before img3 so wait<1> drains it
    cp_w(sW1, g_w[3], tid);
    cp_wait<1>();                      // img2 + h2 ready (img3 in flight)
    __syncthreads();

    // p2: += h2 @ U2[k0]
    gemm_half(sAH, sW0, acc, 0, mBase, nBase, g, ctg);
    __syncthreads();
    cp_w(sW0, g_w[4], tid);
    cp_wait<1>();
    __syncthreads();

    // p3: += h2 @ U2[k1]
    gemm_half(sAH, sW1, acc, 64, mBase, nBase, g, ctg);
    __syncthreads();                   // all stage-1 A reads done
    cp_w(sW1, g_w[5], tid);
    // stage h (fp32) into sAH
#pragma unroll
    for (int t = 0; t < 8; ++t) {
        const float* a4 = acc + t * 4;
        int r0 = mBase + g;
        int c  = nBase + t * 8 + 2 * ctg;
        *reinterpret_cast<float2*>(&sAH[r0 * LDA + c]) = make_float2(a4[0], a4[1]);
        *reinterpret_cast<float2*>(&sAH[(r0 + 8) * LDA + c]) = make_float2(a4[2], a4[3]);
    }
    cp_wait<1>();
    __syncthreads();                   // h visible

    float gate[32];

    // p4: r k0
#pragma unroll
    for (int i = 0; i < 32; ++i) acc[i] = 0.0f;
    gemm_half(sAH, sW0, acc, 0, mBase, nBase, g, ctg);
    __syncthreads();
    cp_w(sW0, g_w[6], tid);
    cp_wait<1>();
    __syncthreads();

    // p5: r k1 + epilogue r
    gemm_half(sAH, sW1, acc, 64, mBase, nBase, g, ctg);
    epilogue<0>(acc, gate, sAH, sX, sWi, sBi, sBhn, mBase, nBase, g, ctg);
    __syncthreads();
    cp_w(sW1, g_w[7], tid);
    cp_wait<1>();
    __syncthreads();

    // p6: n k0
#pragma unroll
    for (int i = 0; i < 32; ++i) acc[i] = 0.0f;
    gemm_half(sAH, sW0, acc, 0, mBase, nBase, g, ctg);
    __syncthreads();
    cp_w(sW0, g_w[8], tid);
    cp_wait<1>();
    __syncthreads();

    // p7: n k1 + epilogue n
    gemm_half(sAH, sW1, acc, 64, mBase, nBase, g, ctg);
    epilogue<1>(acc, gate, sAH, sX, sWi, sBi, sBhn, mBase, nBase, g, ctg);
    __syncthreads();
    cp_w(sW1, g_w[9], tid);
    cp_wait<1>();
    __syncthreads();

    // p8: z k0
#pragma unroll
    for (int i = 0; i < 32; ++i) acc[i] = 0.0f;
    gemm_half(sAH, sW0, acc, 0, mBase, nBase, g, ctg);
    cp_wait<0>();                      // img9 fully landed
    __syncthreads();

    // p9: z k1, then blend into sAH
    gemm_half(sAH, sW1, acc, 64, mBase, nBase, g, ctg);
    __syncthreads();                   // all h reads done before blend writes
    epilogue<2>(acc, gate, sAH, sX, sWi, sBi, sBhn, mBase, nBase, g, ctg);
    __syncthreads();

    // coalesced writeback (x2 for the (new_h, new_h) tuple)
    float* o0 = out + rowBase * DHID;
#pragma unroll
    for (int it = 0; it < 8; ++it) {
        int i  = it * NTHREADS + tid;
        int r  = i >> 5;
        int c4 = (i & 31) << 2;
        float4 v = *reinterpret_cast<const float4*>(sAH + r * LDA + c4);
        *reinterpret_cast<float4*>(o0 + (long)r * DHID + c4) = v;
        if (dup_off)
            *reinterpret_cast<float4*>(o0 + dup_off + (long)r * DHID + c4) = v;
    }
}

extern "C" void kernel_launch(void* const* d_in, const int* in_sizes, int n_in,
                              void* d_out, int out_size) {
    cudaFuncSetAttribute(twodrnn_kernel,
                         cudaFuncAttributeMaxDynamicSharedMemorySize, SMEM_BYTES);

    const float* x    = (const float*)d_in[0];
    const float* h1   = (const float*)d_in[1];
    const float* h2   = (const float*)d_in[2];
    const float* U1   = (const float*)d_in[3];
    const float* U2   = (const float*)d_in[4];
    const float* Wi   = (const float*)d_in[5];
    const float* bi   = (const float*)d_in[6];
    const float* Whrz = (const float*)d_in[7];
    const float* Whn  = (const float*)d_in[8];
    const float* bhn  = (const float*)d_in[9];

    const int Brows = in_sizes[1] / DHID;            // 262144
    const int grid  = Brows / TILE_M;                // 4096
    const long base = (long)Brows * DHID;
    const long dup_off = ((long)out_size >= 2 * base) ? base : 0;

    preround<<<640, 128>>>(U1, U2, Whrz, Whn);
    twodrnn_kernel<<<grid, NTHREADS, SMEM_BYTES>>>(
        x, h1, h2, Wi, bi, bhn, (float*)d_out, dup_off);
}

// round 16
// speedup vs baseline: 1.2197x; 1.0226x over previous
#include <cuda_runtime.h>
#include <cstdint>

// ---------------------------------------------------------------------------
// TwoDRNN (mma.sync tf32): h = h1@U1 + h2@U2 ; GRU(h,x) -> new_h (x2)
// R16: TILE_M=64, 256 thr, warp tile m32n32 (2m x 4n grid) -> LDS-traffic
//      minimal tiling (16KB/CTA/ks vs 20KB at m16n64), 2 CTAs/SM kept.
//      B pre-packed float4 quads (1 LDS.128 -> 2 MMAs), weights double-
//      buffered via cp.async (10 K=64 phases), h tiles via cp.async.
// ---------------------------------------------------------------------------

#define DHID 128
#define TILE_M 64
#define NTHREADS 256

constexpr int LDA = 132;                        // A/H rows: banks 4g+ctg conflict-free

// smem layout (floats)
constexpr int OFF_AH  = 0;                      // 64 x 132 (h tile / h fp32)
constexpr int OFF_W0  = OFF_AH + TILE_M * LDA;  // 8448   (8192: K=64 half image)
constexpr int OFF_W1  = OFF_W0 + 8192;          // 16640
constexpr int OFF_X   = OFF_W1 + 8192;          // 24832
constexpr int OFF_WI  = OFF_X  + TILE_M * 4;    // 25088
constexpr int OFF_BI  = OFF_WI + 1536;          // 26624
constexpr int OFF_BHN = OFF_BI + 384;           // 27008
constexpr int SMEM_FLOATS = OFF_BHN + 128;      // 27136
constexpr int SMEM_BYTES  = SMEM_FLOATS * 4;    // 108544 B -> 2 CTAs/SM

// Pre-rounded tf32 weight half-images (K=64, N=128), float4-quad packed:
// imgs: 0,1: U1 k0,k1  2,3: U2  4,5: Whr  6,7: Whn  8,9: Whz
// float offset = ks*1024 + ng*128 + g*16 + ctg*4 + c, quad c =
//   {W[kb+ctg][n], W[kb+ctg+4][n], W[kb+ctg][n+8], W[kb+ctg+4][n+8]},
//   n = ng*16 + g, kb = half*64 + ks*8.
__device__ float g_w[10][8192];

__device__ __forceinline__ unsigned f2tf(float x) {
    unsigned u;
    asm("cvt.rna.tf32.f32 %0, %1;" : "=r"(u) : "f"(x));
    return u;
}

__device__ __forceinline__ void mma8(float* d, unsigned a0, unsigned a1,
                                     unsigned a2, unsigned a3,
                                     unsigned b0, unsigned b1) {
    asm volatile(
        "mma.sync.aligned.m16n8k8.row.col.f32.tf32.tf32.f32 "
        "{%0,%1,%2,%3}, {%4,%5,%6,%7}, {%8,%9}, {%0,%1,%2,%3};"
        : "+f"(d[0]), "+f"(d[1]), "+f"(d[2]), "+f"(d[3])
        : "r"(a0), "r"(a1), "r"(a2), "r"(a3), "r"(b0), "r"(b1));
}

__device__ __forceinline__ float sigmoidf_(float v) {
    return 1.0f / (1.0f + __expf(-v));
}
__device__ __forceinline__ float tanhf_(float v) {
    float c = fminf(fmaxf(v, -15.0f), 15.0f);
    float e = __expf(2.0f * c);
    return (e - 1.0f) / (e + 1.0f);
}

__device__ __forceinline__ void cp16(void* s, const void* g) {
    unsigned sa = (unsigned)__cvta_generic_to_shared(s);
    asm volatile("cp.async.ca.shared.global [%0], [%1], 16;" :: "r"(sa), "l"(g));
}
__device__ __forceinline__ void cp_commit() { asm volatile("cp.async.commit_group;"); }
template <int N>
__device__ __forceinline__ void cp_wait() {
    asm volatile("cp.async.wait_group %0;" :: "n"(N) : "memory");
}

// cp.async one 32KB pre-imaged weight half (contiguous). Commits a group.
__device__ __forceinline__ void cp_w(float* sW, const float* __restrict__ g, int tid) {
#pragma unroll
    for (int it = 0; it < 8; ++it) {
        int i = it * NTHREADS + tid;            // 2048 float4 slots
        cp16(sW + i * 4, g + i * 4);
    }
    cp_commit();
}

// cp.async a 64x128 fp32 h tile into sAH (stride LDA). Commits a group.
__device__ __forceinline__ void cp_h(float* sAH, const float* __restrict__ g, int tid) {
#pragma unroll
    for (int it = 0; it < 8; ++it) {
        int i  = it * NTHREADS + tid;           // 2048 float4 slots
        int r  = i >> 5;
        int c4 = (i & 31) << 2;
        cp16(sAH + r * LDA + c4, g + (long)r * DHID + c4);
    }
    cp_commit();
}

// acc += A[mBase:+32, kA0:+64] @ Whalf[:, nBase:+32]  (8 k8-steps).
// acc[(mt*4 + nt)*4 + q], mt in 0..1, nt in 0..3.
// A raw fp32 in smem, rna-rounded in-loop. B via LDS.128 quads (2 per ks).
__device__ __forceinline__ void gemm_half(const float* sA, const float* sW,
                                          float acc[32], int kA0,
                                          int mBase, int nBase, int g, int ctg) {
    const int ngBase = nBase >> 4;              // 0,2,4,6
#pragma unroll
    for (int ks = 0; ks < 8; ++ks) {
        const int kA = kA0 + ks * 8;
        unsigned a[2][4];
#pragma unroll
        for (int mt = 0; mt < 2; ++mt) {
            const float* ar0 = sA + (mBase + mt * 16 + g) * LDA + kA;
            const float* ar1 = ar0 + 8 * LDA;
            a[mt][0] = f2tf(ar0[ctg]);
            a[mt][1] = f2tf(ar1[ctg]);
            a[mt][2] = f2tf(ar0[ctg + 4]);
            a[mt][3] = f2tf(ar1[ctg + 4]);
        }
        const float* bp = sW + ks * 1024 + ngBase * 128 + g * 16 + ctg * 4;
#pragma unroll
        for (int tp = 0; tp < 2; ++tp) {
            float4 b = *reinterpret_cast<const float4*>(bp + tp * 128);
            unsigned b0 = __float_as_uint(b.x);
            unsigned b1 = __float_as_uint(b.y);
            unsigned b2 = __float_as_uint(b.z);
            unsigned b3 = __float_as_uint(b.w);
#pragma unroll
            for (int mt = 0; mt < 2; ++mt) {
                mma8(acc + (mt * 4 + 2 * tp) * 4, a[mt][0], a[mt][1], a[mt][2], a[mt][3], b0, b1);
                mma8(acc + (mt * 4 + 2 * tp + 1) * 4, a[mt][0], a[mt][1], a[mt][2], a[mt][3], b2, b3);
            }
        }
    }
}

// GRU epilogue for chunk CH (0: r, 1: n in-place, 2: z + blend into sAH).
// Index map matches gemm: idx = (mt*4 + nt)*4 + qh*2 + ql,
// rr = mBase + mt*16 + g + qh*8, cc = nBase + nt*8 + 2*ctg + ql.
template <int CH>
__device__ __forceinline__ void epilogue(const float acc[32], float gate[32],
                                         float* sAH, const float* sX,
                                         const float* sWi, const float* sBi,
                                         const float* sBhn,
                                         int mBase, int nBase, int g, int ctg) {
    float xv[4][4];
#pragma unroll
    for (int mt = 0; mt < 2; ++mt)
#pragma unroll
        for (int qh = 0; qh < 2; ++qh) {
            int rr = mBase + mt * 16 + g + qh * 8;
#pragma unroll
            for (int k = 0; k < 4; ++k) xv[mt * 2 + qh][k] = sX[rr * 4 + k];
        }
#pragma unroll
    for (int nt = 0; nt < 4; ++nt) {
#pragma unroll
        for (int ql = 0; ql < 2; ++ql) {
            const int cc = nBase + nt * 8 + 2 * ctg + ql;
            const int j  = cc + (CH == 0 ? 0 : (CH == 1 ? 256 : 128));
            const float w0 = sWi[0 * 384 + j];
            const float w1 = sWi[1 * 384 + j];
            const float w2 = sWi[2 * 384 + j];
            const float w3 = sWi[3 * 384 + j];
            const float bb = sBi[j];
            const float bh = (CH == 1) ? sBhn[cc] : 0.0f;
#pragma unroll
            for (int mt = 0; mt < 2; ++mt)
#pragma unroll
                for (int qh = 0; qh < 2; ++qh) {
                    const int idx = (mt * 4 + nt) * 4 + qh * 2 + ql;
                    const float* xp = xv[mt * 2 + qh];
                    float ip = bb + xp[0] * w0 + xp[1] * w1
                                  + xp[2] * w2 + xp[3] * w3;
                    const float v = acc[idx];
                    if (CH == 0) {
                        gate[idx] = sigmoidf_(ip + v);                  // r
                    } else if (CH == 1) {
                        gate[idx] = tanhf_(ip + gate[idx] * (v + bh));  // n
                    } else {
                        const int rr = mBase + mt * 16 + g + qh * 8;
                        float z  = sigmoidf_(ip + v);
                        float hv = sAH[rr * LDA + cc];
                        sAH[rr * LDA + cc] = (1.0f - z) * gate[idx] + z * hv;
                    }
                }
        }
    }
}

// Offline: round weights to tf32-rna and pack float4 quads.
__global__ void preround(const float* __restrict__ U1, const float* __restrict__ U2,
                         const float* __restrict__ Whrz, const float* __restrict__ Whn) {
    const int idx = blockIdx.x * blockDim.x + threadIdx.x;   // < 81920
    const int img  = idx >> 13;         // 0..9
    const int o    = idx & 8191;
    const int ks   = o >> 10;
    const int r    = o & 1023;
    const int ng   = r >> 7;
    const int q    = r & 127;
    const int g    = q >> 4;
    const int w    = q & 15;
    const int ctg  = w >> 2;
    const int c    = w & 3;
    const int gi   = img >> 1;
    const int half = img & 1;
    const int n    = ng * 16 + g + (c >> 1) * 8;
    const int k    = half * 64 + ks * 8 + ctg + (c & 1) * 4;
    float v;
    if      (gi == 0) v = U1[k * 128 + n];
    else if (gi == 1) v = U2[k * 128 + n];
    else if (gi == 2) v = Whrz[k * 256 + n];
    else if (gi == 3) v = Whn[k * 128 + n];
    else              v = Whrz[k * 256 + 128 + n];
    g_w[img][o] = __uint_as_float(f2tf(v));
}

__global__ __launch_bounds__(NTHREADS, 2)
void twodrnn_kernel(const float* __restrict__ x,
                    const float* __restrict__ h1,
                    const float* __restrict__ h2,
                    const float* __restrict__ Wi,
                    const float* __restrict__ bi,
                    const float* __restrict__ bhn,
                    float* __restrict__ out, long dup_off) {
    extern __shared__ float sm[];
    float* sAH  = sm + OFF_AH;
    float* sW0  = sm + OFF_W0;
    float* sW1  = sm + OFF_W1;
    float* sX   = sm + OFF_X;
    float* sWi  = sm + OFF_WI;
    float* sBi  = sm + OFF_BI;
    float* sBhn = sm + OFF_BHN;

    const int tid  = threadIdx.x;
    const int warp = tid >> 5;
    const int lane = tid & 31;
    const int g    = lane >> 2;
    const int ctg  = lane & 3;
    const int mBase = (warp & 1) * 32;   // 2 m-groups of 32
    const int nBase = (warp >> 1) * 32;  // 4 n-groups of 32
    const long rowBase = (long)blockIdx.x * TILE_M;

    // prologue: h1 (group), img0 (group), img1 (group), small params
    cp_h(sAH, h1 + rowBase * DHID, tid);
    cp_w(sW0, g_w[0], tid);
    cp_w(sW1, g_w[1], tid);
    for (int i = tid; i < 1536; i += NTHREADS) sWi[i] = Wi[i];
    for (int i = tid; i < 384; i += NTHREADS)  sBi[i] = bi[i];
    for (int i = tid; i < 128; i += NTHREADS)  sBhn[i] = bhn[i];
    for (int i = tid; i < TILE_M * 4; i += NTHREADS) sX[i] = x[rowBase * 4 + i];
    cp_wait<1>();                      // h1 + img0 landed (img1 in flight)
    __syncthreads();

    float acc[32];
#pragma unroll
    for (int i = 0; i < 32; ++i) acc[i] = 0.0f;

    // p0: h1 @ U1[k0]
    gemm_half(sAH, sW0, acc, 0, mBase, nBase, g, ctg);
    __syncthreads();
    cp_w(sW0, g_w[2], tid);
    cp_wait<1>();                      // img1 ready
    __syncthreads();

    // p1: h1 @ U1[k1]
    gemm_half(sAH, sW1, acc, 64, mBase, nBase, g, ctg);
    __syncthreads();                   // h1 reads done
    cp_h(sAH, h2 + rowBase * DHID, tid);   // before img3 so wait<1> drains it
    cp_w(sW1, g_w[3], tid);
    cp_wait<1>();                      // img2 + h2 ready (img3 in flight)
    __syncthreads();

    // p2: += h2 @ U2[k0]
    gemm_half(sAH, sW0, acc, 0, mBase, nBase, g, ctg);
    __syncthreads();
    cp_w(sW0, g_w[4], tid);
    cp_wait<1>();
    __syncthreads();

    // p3: += h2 @ U2[k1]
    gemm_half(sAH, sW1, acc, 64, mBase, nBase, g, ctg);
    __syncthreads();                   // all stage-1 A reads done
    cp_w(sW1, g_w[5], tid);
    // stage h (fp32) into sAH
#pragma unroll
    for (int mt = 0; mt < 2; ++mt)
#pragma unroll
        for (int nt = 0; nt < 4; ++nt) {
            const float* a4 = acc + (mt * 4 + nt) * 4;
            int r0 = mBase + mt * 16 + g;
            int c  = nBase + nt * 8 + 2 * ctg;
            *reinterpret_cast<float2*>(&sAH[r0 * LDA + c]) = make_float2(a4[0], a4[1]);
            *reinterpret_cast<float2*>(&sAH[(r0 + 8) * LDA + c]) = make_float2(a4[2], a4[3]);
        }
    cp_wait<1>();
    __syncthreads();                   // h visible

    float gate[32];

    // p4: r k0
#pragma unroll
    for (int i = 0; i < 32; ++i) acc[i] = 0.0f;
    gemm_half(sAH, sW0, acc, 0, mBase, nBase, g, ctg);
    __syncthreads();
    cp_w(sW0, g_w[6], tid);
    cp_wait<1>();
    __syncthreads();

    // p5: r k1 + epilogue r
    gemm_half(sAH, sW1, acc, 64, mBase, nBase, g, ctg);
    epilogue<0>(acc, gate, sAH, sX, sWi, sBi, sBhn, mBase, nBase, g, ctg);
    __syncthreads();
    cp_w(sW1, g_w[7], tid);
    cp_wait<1>();
    __syncthreads();

    // p6: n k0
#pragma unroll
    for (int i = 0; i < 32; ++i) acc[i] = 0.0f;
    gemm_half(sAH, sW0, acc, 0, mBase, nBase, g, ctg);
    __syncthreads();
    cp_w(sW0, g_w[8], tid);
    cp_wait<1>();
    __syncthreads();

    // p7: n k1 + epilogue n
    gemm_half(sAH, sW1, acc, 64, mBase, nBase, g, ctg);
    epilogue<1>(acc, gate, sAH, sX, sWi, sBi, sBhn, mBase, nBase, g, ctg);
    __syncthreads();
    cp_w(sW1, g_w[9], tid);
    cp_wait<1>();
    __syncthreads();

    // p8: z k0
#pragma unroll
    for (int i = 0; i < 32; ++i) acc[i] = 0.0f;
    gemm_half(sAH, sW0, acc, 0, mBase, nBase, g, ctg);
    cp_wait<0>();                      // img9 fully landed
    __syncthreads();

    // p9: z k1, then blend into sAH
    gemm_half(sAH, sW1, acc, 64, mBase, nBase, g, ctg);
    __syncthreads();                   // all h reads done before blend writes
    epilogue<2>(acc, gate, sAH, sX, sWi, sBi, sBhn, mBase, nBase, g, ctg);
    __syncthreads();

    // coalesced writeback (x2 for the (new_h, new_h) tuple)
    float* o0 = out + rowBase * DHID;
#pragma unroll
    for (int it = 0; it < 8; ++it) {
        int i  = it * NTHREADS + tid;
        int r  = i >> 5;
        int c4 = (i & 31) << 2;
        float4 v = *reinterpret_cast<const float4*>(sAH + r * LDA + c4);
        *reinterpret_cast<float4*>(o0 + (long)r * DHID + c4) = v;
        if (dup_off)
            *reinterpret_cast<float4*>(o0 + dup_off + (long)r * DHID + c4) = v;
    }
}

extern "C" void kernel_launch(void* const* d_in, const int* in_sizes, int n_in,
                              void* d_out, int out_size) {
    cudaFuncSetAttribute(twodrnn_kernel,
                         cudaFuncAttributeMaxDynamicSharedMemorySize, SMEM_BYTES);

    const float* x    = (const float*)d_in[0];
    const float* h1   = (const float*)d_in[1];
    const float* h2   = (const float*)d_in[2];
    const float* U1   = (const float*)d_in[3];
    const float* U2   = (const float*)d_in[4];
    const float* Wi   = (const float*)d_in[5];
    const float* bi   = (const float*)d_in[6];
    const float* Whrz = (const float*)d_in[7];
    const float* Whn  = (const float*)d_in[8];
    const float* bhn  = (const float*)d_in[9];

    const int Brows = in_sizes[1] / DHID;            // 262144
    const int grid  = Brows / TILE_M;                // 4096
    const long base = (long)Brows * DHID;
    const long dup_off = ((long)out_size >= 2 * base) ? base : 0;

    preround<<<640, 128>>>(U1, U2, Whrz, Whn);
    twodrnn_kernel<<<grid, NTHREADS, SMEM_BYTES>>>(
        x, h1, h2, Wi, bi, bhn, (float*)d_out, dup_off);
}